// round 5
// baseline (speedup 1.0000x reference)
#include <cuda_runtime.h>

#define G 1024
#define NBLOCKS 512  // grid 16 x 32; block 32x8; tile 64 cols x 32 rows of nodes

__device__ float2 g_part[NBLOCKS];
__device__ unsigned int g_cnt = 0;

#define C11 (1.0f / 0.91f)
#define C12 (0.3f / 0.91f)
#define C33 (0.35f / 0.91f)
#define A2c (2.0f * (C11 + C33))
#define BGc (0.5f * (C12 + C33))

#define SU_ROWS 34   // node rows -1 .. +32 (clamped)
#define ST_ROWS 33   // node rows  0 .. +32 (clamped)
#define S_COLS 66    // su: node cols -1..+64 ; st: cols 0..+64 (col 65 zero pad)

// tri1 (corners a, b=a+j, c=a+i): s = C * d
#define TRI1(s0, s1, s2, ua, ub, uc)                                        \
    {                                                                       \
        float d0 = (uc).x - (ua).x;                                         \
        float d1 = (ub).y - (ua).y;                                         \
        float d2 = (ub).x + (uc).y - (ua).x - (ua).y;                       \
        s0 = C11 * d0 + C12 * d1;                                           \
        s1 = C12 * d0 + C11 * d1;                                           \
        s2 = C33 * d2;                                                      \
    }
// tri2 (corners b, d=b+i, c=d-j)
#define TRI2(t0, t1, t2, ub, ud, uc)                                        \
    {                                                                       \
        float e0 = (ud).x - (ub).x;                                         \
        float e1 = (ud).y - (uc).y;                                         \
        float e2 = (ud).x + (ud).y - (ub).y - (uc).x;                       \
        t0 = C11 * e0 + C12 * e1;                                           \
        t1 = C12 * e0 + C11 * e1;                                           \
        t2 = C33 * e2;                                                      \
    }

// residual at node (i, jc); clamp baked into window values, masks kill invalid cells
__device__ __forceinline__ void node_R(
    float2 u01, float2 u02,
    float2 u10, float2 u11, float2 u12,
    float2 u20, float2 u21,
    bool interior, int i, int jc, float& Rx, float& Ry) {
    if (interior) {
        float Vx = u01.x + u21.x, Hx = u10.x + u12.x;
        float Vy = u01.y + u21.y, Hy = u10.y + u12.y;
        float Tx = 2.f * u11.x - Vx - Hx + u20.x + u02.x;
        float Ty = 2.f * u11.y - Vy - Hy + u20.y + u02.y;
        Rx = A2c * u11.x - C11 * Vx - C33 * Hx + BGc * Ty;
        Ry = A2c * u11.y - C11 * Hy - C33 * Vy + BGc * Tx;
    } else {
        const float mA = (i < G - 1 && jc < G - 1) ? 1.f : 0.f;
        const float mB = (i < G - 1 && jc > 0) ? 1.f : 0.f;
        const float mC = (i > 0 && jc < G - 1) ? 1.f : 0.f;
        const float mD = (i > 0 && jc > 0) ? 1.f : 0.f;
        float sA0, sA1, sA2; TRI1(sA0, sA1, sA2, u11, u12, u21);
        float sB0, sB1, sB2; TRI1(sB0, sB1, sB2, u10, u11, u20);
        float tB0, tB1, tB2; TRI2(tB0, tB1, tB2, u11, u21, u20);
        float sC0, sC1, sC2; TRI1(sC0, sC1, sC2, u01, u02, u11);
        float tC0, tC1, tC2; TRI2(tC0, tC1, tC2, u02, u12, u11);
        float tD0, tD1, tD2; TRI2(tD0, tD1, tD2, u01, u11, u10);
        (void)sB0; (void)tB1; (void)sC1; (void)tC0;
        Rx = mA * (-0.5f) * (sA0 + sA2) + mB * 0.5f * (sB2 - tB0) +
             mC * 0.5f * (sC0 - tC2)    + mD * 0.5f * (tD0 + tD2);
        Ry = mA * (-0.5f) * (sA1 + sA2) + mB * 0.5f * (sB1 - tB2) +
             mC * 0.5f * (sC2 - tC1)    + mD * 0.5f * (tD1 + tD2);
    }
}

// energy of one cell with error corners a=(i,j) b=(i,j+1) c=(i+1,j) d=(i+1,j+1)
__device__ __forceinline__ float cell_E(float2 a, float2 b, float2 c, float2 d) {
    float d0 = c.x - a.x, d1 = b.y - a.y, d2 = b.x + c.y - a.x - a.y;
    float e0 = d.x - b.x, e1 = d.y - c.y, e2 = d.x + d.y - b.y - c.x;
    return C11 * (d0 * d0 + d1 * d1) + 2.f * C12 * (d0 * d1) + C33 * (d2 * d2) +
           C11 * (e0 * e0 + e1 * e1) + 2.f * C12 * (e0 * e1) + C33 * (e2 * e2);
}

// read 4 consecutive float2 cols from a smem row (16B-aligned: cl even, row stride 66*8=33*16)
__device__ __forceinline__ void ld_row4(const float2* s, int r, int cl,
                                        float2& a, float2& b, float2& c, float2& d) {
    const float4* p = reinterpret_cast<const float4*>(s + r * S_COLS + cl);
    float4 lo = p[0], hi = p[1];
    a = make_float2(lo.x, lo.y); b = make_float2(lo.z, lo.w);
    c = make_float2(hi.x, hi.y); d = make_float2(hi.z, hi.w);
}

__global__ __launch_bounds__(256, 4) void pino_fused_kernel(
    const float2* __restrict__ up, const float2* __restrict__ ut,
    float* __restrict__ out) {
    __shared__ float2 su[SU_ROWS * S_COLS];  // u_pred tile + halo, clamped
    __shared__ float2 st[ST_ROWS * S_COLS];  // u_true tile, clamped, col 65 = 0

    const int tx = threadIdx.x, ty = threadIdx.y;
    const int tid = ty * 32 + tx;
    const int j0 = blockIdx.x * 64, i0 = blockIdx.y * 32;

    // ---- cooperative load (coalesced along columns) ----
    for (int idx = tid; idx < SU_ROWS * S_COLS; idx += 256) {
        int r = idx / S_COLS, c = idx - r * S_COLS;
        int gi = min(max(i0 - 1 + r, 0), G - 1);
        int gj = min(max(j0 - 1 + c, 0), G - 1);
        su[idx] = __ldg(&up[gi * G + gj]);
    }
    for (int idx = tid; idx < ST_ROWS * S_COLS; idx += 256) {
        int r = idx / S_COLS, c = idx - r * S_COLS;
        if (c < 65) {
            int gi = min(i0 + r, G - 1);
            int gj = min(j0 + c, G - 1);
            st[idx] = __ldg(&ut[gi * G + gj]);
        } else {
            st[idx] = make_float2(0.f, 0.f);
        }
    }
    __syncthreads();

    // ---- compute: each thread owns 2 cols x 4 rows ----
    const int cl = 2 * tx;            // su/st local col base (su col cl == node col j-1)
    const int jA = j0 + cl;           // node A global col (even)
    const int n0 = 4 * ty;            // first local node row
    const bool jintA = (jA > 0) && (jA < G - 1);
    const bool jintB = (jA + 1 < G - 1);

    float2 am, bm, cm, dm, ac, bc, cc, dc, an, bn, cn, dn;  // 3-row window, 4 cols
    ld_row4(su, n0, cl, am, bm, cm, dm);          // node row n0-1 (su row n0)
    ld_row4(su, n0 + 1, cl, ac, bc, cc, dc);      // node row n0
    ld_row4(su, n0 + 2, cl, an, bn, cn, dn);      // node row n0+1
    float2 ta, tb, tcx, tdx;
    ld_row4(st, n0, cl, ta, tb, tcx, tdx);        // ut node row n0 (cols j..j+3)
    (void)tdx;

    float vr = 0.f, ve = 0.f;

    #pragma unroll
    for (int k = 0; k < 4; k++) {
        const int i = i0 + n0 + k;
        float2 ua, ub, uc, ud;
        ld_row4(st, n0 + k + 1, cl, ua, ub, uc, ud);  // ut row i+1
        (void)ud;

        const bool iint = (i > 0) && (i < G - 1);
        float RxA, RyA, RxB, RyB;
        node_R(bm, cm, ac, bc, cc, an, bn, iint && jintA, i, jA, RxA, RyA);
        node_R(cm, dm, bc, cc, dc, bn, cn, iint && jintB, i, jA + 1, RxB, RyB);
        vr += RxA * RxA + RyA * RyA + RxB * RxB + RyB * RyB;

        // energy of cells (i, jA) and (i, jA+1) on u_err (x0.5 at final combine)
        if (i < G - 1) {
            float2 E10 = make_float2(bc.x - ta.x, bc.y - ta.y);
            float2 E11 = make_float2(cc.x - tb.x, cc.y - tb.y);
            float2 E20 = make_float2(bn.x - ua.x, bn.y - ua.y);
            float2 E21 = make_float2(cn.x - ub.x, cn.y - ub.y);
            ve += cell_E(E10, E11, E20, E21);
            if (jA < G - 2) {
                float2 E12 = make_float2(dc.x - tcx.x, dc.y - tcx.y);
                float2 E22 = make_float2(dn.x - uc.x, dn.y - uc.y);
                ve += cell_E(E11, E12, E21, E22);
            }
        }

        // roll window (register renaming; loop fully unrolled)
        am = ac; bm = bc; cm = cc; dm = dc;
        ac = an; bc = bn; cc = cn; dc = dn;
        if (k < 3) ld_row4(su, n0 + k + 3, cl, an, bn, cn, dn);
        ta = ua; tb = ub; tcx = uc;
    }

    // ---- block reduction ----
    #pragma unroll
    for (int o = 16; o; o >>= 1) {
        vr += __shfl_down_sync(0xFFFFFFFFu, vr, o);
        ve += __shfl_down_sync(0xFFFFFFFFu, ve, o);
    }
    __shared__ float sr[8], se[8];
    __shared__ unsigned s_last;
    if (tx == 0) { sr[ty] = vr; se[ty] = ve; }
    __syncthreads();
    if (tid == 0) {
        float a = 0.f, b = 0.f;
        #pragma unroll
        for (int q = 0; q < 8; q++) { a += sr[q]; b += se[q]; }
        int bid = blockIdx.y * gridDim.x + blockIdx.x;
        g_part[bid] = make_float2(a, b);
        __threadfence();
        unsigned old = atomicAdd(&g_cnt, 1u);
        s_last = (old == NBLOCKS - 1) ? 1u : 0u;
    }
    __syncthreads();

    // ---- last block finishes (fixed order -> deterministic) ----
    if (s_last) {
        double a = 0.0, b = 0.0;
        #pragma unroll
        for (int q = 0; q < NBLOCKS / 256; q++) {
            float2 v = g_part[q * 256 + tid];
            a += (double)v.x;
            b += (double)v.y;
        }
        #pragma unroll
        for (int o = 16; o; o >>= 1) {
            a += __shfl_down_sync(0xFFFFFFFFu, a, o);
            b += __shfl_down_sync(0xFFFFFFFFu, b, o);
        }
        __shared__ double dr[8], de[8];
        if (tx == 0) { dr[ty] = a; de[ty] = b; }
        __syncthreads();
        if (tid == 0) {
            double ta2 = 0.0, tb2 = 0.0;
            #pragma unroll
            for (int q = 0; q < 8; q++) { ta2 += dr[q]; tb2 += de[q]; }
            double leq = ta2 / (2.0 * (double)G * (double)G);  // mean(R^2)
            double len = 0.5 * tb2;  // total_area telescopes to 1.0
            out[0] = (float)(0.1 * leq + 0.1 * len);
            g_cnt = 0;  // reset for next graph replay
        }
    }
}

extern "C" void kernel_launch(void* const* d_in, const int* in_sizes, int n_in,
                              void* d_out, int out_size) {
    const float2* up = (const float2*)d_in[0];  // u_pred (N,2)
    const float2* ut = (const float2*)d_in[1];  // u_true (N,2)
    (void)in_sizes; (void)n_in; (void)out_size;

    dim3 blk(32, 8);
    dim3 grd(G / 64, G / 32);  // 16 x 32 = 512 blocks, one wave
    pino_fused_kernel<<<grd, blk>>>(up, ut, (float*)d_out);
}

// round 7
// speedup vs baseline: 1.0892x; 1.0892x over previous
#include <cuda_runtime.h>

#define G 1024
#define RPT 8
#define NBLOCKS 512  // grid 32 x 16, block 32x8, 8 nodes/thread vertically

__device__ float2 g_part[NBLOCKS];
__device__ unsigned int g_cnt = 0;

#define C11 (1.0f / 0.91f)
#define C12 (0.3f / 0.91f)
#define C33 (0.35f / 0.91f)
#define A2c (2.0f * (C11 + C33))
#define BGc (0.5f * (C12 + C33))

// tri1 of a cell (corners a, b=a+j, c=a+i): s = C * d
#define TRI1(s0, s1, s2, ua, ub, uc)                                        \
    {                                                                       \
        float d0 = (uc).x - (ua).x;                                         \
        float d1 = (ub).y - (ua).y;                                         \
        float d2 = (ub).x + (uc).y - (ua).x - (ua).y;                       \
        s0 = C11 * d0 + C12 * d1;                                           \
        s1 = C12 * d0 + C11 * d1;                                           \
        s2 = C33 * d2;                                                      \
    }
// tri2 of a cell (corners b, d=b+i, c=d-j)
#define TRI2(t0, t1, t2, ub, ud, uc)                                        \
    {                                                                       \
        float e0 = (ud).x - (ub).x;                                         \
        float e1 = (ud).y - (uc).y;                                         \
        float e2 = (ud).x + (ud).y - (ub).y - (uc).x;                       \
        t0 = C11 * e0 + C12 * e1;                                           \
        t1 = C12 * e0 + C11 * e1;                                           \
        t2 = C33 * e2;                                                      \
    }

__global__ __launch_bounds__(256, 5) void pino_fused_kernel(
    const float2* __restrict__ up, const float2* __restrict__ ut,
    float* __restrict__ out) {
    const int j = blockIdx.x * 32 + threadIdx.x;
    const int i0 = (blockIdx.y * 8 + threadIdx.y) * RPT;
    const int djm = (j > 0) ? -1 : 0;           // col offsets baked once
    const int djp = (j < G - 1) ? 1 : 0;
    const bool jint = (j > 0) && (j < G - 1);
    const bool top = (i0 == 0);                  // first node row of grid
    const bool bot = (i0 + RPT == G);            // contains last node row

    // base pointers at (i0, j); all row offsets are compile-time multiples of G
    const float2* __restrict__ pu = up + i0 * G + j;
    const float2* __restrict__ pt = ut + i0 * G + j;

    // rolling 3-row window: pm = row i-1, pc = row i, pn = row i+1
    float2 pm0, pm1, pm2, pc0, pc1, pc2, pn0, pn1, pn2;
    {
        const float2* pr = top ? pu : (pu - G);
        pm0 = __ldg(pr + djm); pm1 = __ldg(pr); pm2 = __ldg(pr + djp);
    }
    pc0 = __ldg(pu + djm); pc1 = __ldg(pu); pc2 = __ldg(pu + djp);
    pn0 = __ldg(pu + G + djm); pn1 = __ldg(pu + G); pn2 = __ldg(pu + G + djp);
    float2 tc0 = __ldg(pt), tc1 = __ldg(pt + djp);

    float vr = 0.f, ve = 0.f;

    #pragma unroll
    for (int k = 0; k < RPT; k++) {
        const int i = i0 + k;
        const bool last = bot && (k == RPT - 1);
        const float2* ptn = pt + (last ? k * G : (k + 1) * G);
        float2 tn0 = __ldg(ptn), tn1 = __ldg(ptn + djp);

        float Rx, Ry;
        if (jint && i > 0 && i < G - 1) {
            // interior 7-point stencil (u00/u22 cancel out)
            float Vx = pm1.x + pn1.x, Hx = pc0.x + pc2.x;
            float Vy = pm1.y + pn1.y, Hy = pc0.y + pc2.y;
            float Tx = 2.f * pc1.x - Vx - Hx + pn0.x + pm2.x;
            float Ty = 2.f * pc1.y - Vy - Hy + pn0.y + pm2.y;
            Rx = A2c * pc1.x - C11 * Vx - C33 * Hx + BGc * Ty;
            Ry = A2c * pc1.y - C11 * Hy - C33 * Vy + BGc * Tx;
        } else {
            // boundary: full masked 6-triangle path (verified rel_err == 0)
            const float mA = (i < G - 1 && j < G - 1) ? 1.f : 0.f;
            const float mB = (i < G - 1 && j > 0) ? 1.f : 0.f;
            const float mC = (i > 0 && j < G - 1) ? 1.f : 0.f;
            const float mD = (i > 0 && j > 0) ? 1.f : 0.f;
            float sA0, sA1, sA2; TRI1(sA0, sA1, sA2, pc1, pc2, pn1);
            float sB0, sB1, sB2; TRI1(sB0, sB1, sB2, pc0, pc1, pn0);
            float tB0, tB1, tB2; TRI2(tB0, tB1, tB2, pc1, pn1, pn0);
            float sC0, sC1, sC2; TRI1(sC0, sC1, sC2, pm1, pm2, pc1);
            float tC0, tC1, tC2; TRI2(tC0, tC1, tC2, pm2, pc2, pc1);
            float tD0, tD1, tD2; TRI2(tD0, tD1, tD2, pm1, pc1, pc0);
            (void)sB0; (void)tB1; (void)sC1; (void)tC0;
            Rx = mA * (-0.5f) * (sA0 + sA2) + mB * 0.5f * (sB2 - tB0) +
                 mC * 0.5f * (sC0 - tC2)    + mD * 0.5f * (tD0 + tD2);
            Ry = mA * (-0.5f) * (sA1 + sA2) + mB * 0.5f * (sB1 - tB2) +
                 mC * 0.5f * (sC2 - tC1)    + mD * 0.5f * (tD1 + tD2);
        }
        vr += Rx * Rx + Ry * Ry;

        // energy of cell (i,j) on u_err; (x0.5 applied at final combine)
        if (!last && j < G - 1) {
            float eax = pc1.x - tc0.x, eay = pc1.y - tc0.y;
            float ebx = pc2.x - tc1.x, eby = pc2.y - tc1.y;
            float ecx = pn1.x - tn0.x, ecy = pn1.y - tn0.y;
            float edx = pn2.x - tn1.x, edy = pn2.y - tn1.y;
            float d0 = ecx - eax, d1 = eby - eay, d2 = ebx + ecy - eax - eay;
            float e0 = edx - ebx, e1 = edy - ecy, e2 = edx + edy - eby - ecx;
            ve += C11 * (d0 * d0 + d1 * d1) + 2.f * C12 * (d0 * d1) +
                  C33 * (d2 * d2) +
                  C11 * (e0 * e0 + e1 * e1) + 2.f * C12 * (e0 * e1) +
                  C33 * (e2 * e2);
        }

        // roll the window down one row
        pm0 = pc0; pm1 = pc1; pm2 = pc2;
        pc0 = pn0; pc1 = pn1; pc2 = pn2;
        if (k < RPT - 1) {
            const float2* pr = pu + ((bot && k == RPT - 2) ? (k + 1) : (k + 2)) * G;
            pn0 = __ldg(pr + djm); pn1 = __ldg(pr); pn2 = __ldg(pr + djp);
        }
        tc0 = tn0; tc1 = tn1;
    }

    // ---- block reduction ----
    #pragma unroll
    for (int o = 16; o; o >>= 1) {
        vr += __shfl_down_sync(0xFFFFFFFFu, vr, o);
        ve += __shfl_down_sync(0xFFFFFFFFu, ve, o);
    }
    __shared__ float sr[8], se[8];
    __shared__ unsigned s_last;
    if (threadIdx.x == 0) { sr[threadIdx.y] = vr; se[threadIdx.y] = ve; }
    __syncthreads();
    if (threadIdx.x == 0 && threadIdx.y == 0) {
        float a = 0.f, b = 0.f;
        #pragma unroll
        for (int q = 0; q < 8; q++) { a += sr[q]; b += se[q]; }
        int bid = blockIdx.y * gridDim.x + blockIdx.x;
        g_part[bid] = make_float2(a, b);
        __threadfence();
        unsigned old = atomicAdd(&g_cnt, 1u);
        s_last = (old == NBLOCKS - 1) ? 1u : 0u;
    }
    __syncthreads();

    // ---- last block finishes the global reduction (fixed order -> deterministic) ----
    if (s_last) {
        const int t = threadIdx.y * 32 + threadIdx.x;  // 0..255
        double a = 0.0, b = 0.0;
        #pragma unroll
        for (int q = 0; q < NBLOCKS / 256; q++) {
            float2 v = g_part[q * 256 + t];
            a += (double)v.x;
            b += (double)v.y;
        }
        #pragma unroll
        for (int o = 16; o; o >>= 1) {
            a += __shfl_down_sync(0xFFFFFFFFu, a, o);
            b += __shfl_down_sync(0xFFFFFFFFu, b, o);
        }
        __shared__ double dr[8], de[8];
        if ((t & 31) == 0) { dr[t >> 5] = a; de[t >> 5] = b; }
        __syncthreads();
        if (t == 0) {
            double ta = 0.0, tb = 0.0;
            #pragma unroll
            for (int q = 0; q < 8; q++) { ta += dr[q]; tb += de[q]; }
            double leq = ta / (2.0 * (double)G * (double)G);  // mean(R^2)
            double len = 0.5 * tb;  // total_area telescopes to 1.0
            out[0] = (float)(0.1 * leq + 0.1 * len);
            g_cnt = 0;  // reset for next graph replay
        }
    }
}

extern "C" void kernel_launch(void* const* d_in, const int* in_sizes, int n_in,
                              void* d_out, int out_size) {
    const float2* up = (const float2*)d_in[0];  // u_pred (N,2)
    const float2* ut = (const float2*)d_in[1];  // u_true (N,2)
    (void)in_sizes; (void)n_in; (void)out_size;

    dim3 blk(32, 8);
    dim3 grd(G / 32, G / (8 * RPT));  // 32 x 16 = 512 blocks, one wave
    pino_fused_kernel<<<grd, blk>>>(up, ut, (float*)d_out);
}

// round 8
// speedup vs baseline: 1.1554x; 1.0608x over previous
#include <cuda_runtime.h>

#define G 1024
#define RPT 8
#define NBLOCKS 512  // grid 32 x 16, block 32x8, 8 nodes/thread vertically

__device__ float2 g_part[NBLOCKS];
__device__ unsigned int g_cnt = 0;

#define C11 (1.0f / 0.91f)
#define C12 (0.3f / 0.91f)
#define C33 (0.35f / 0.91f)
#define A2c (2.0f * (C11 + C33))
#define BGc (0.5f * (C12 + C33))

// tri1 of a cell (corners a, b=a+j, c=a+i): s = C * d
#define TRI1(s0, s1, s2, ua, ub, uc)                                        \
    {                                                                       \
        float d0 = (uc).x - (ua).x;                                         \
        float d1 = (ub).y - (ua).y;                                         \
        float d2 = (ub).x + (uc).y - (ua).x - (ua).y;                       \
        s0 = C11 * d0 + C12 * d1;                                           \
        s1 = C12 * d0 + C11 * d1;                                           \
        s2 = C33 * d2;                                                      \
    }
// tri2 of a cell (corners b, d=b+i, c=d-j)
#define TRI2(t0, t1, t2, ub, ud, uc)                                        \
    {                                                                       \
        float e0 = (ud).x - (ub).x;                                         \
        float e1 = (ud).y - (uc).y;                                         \
        float e2 = (ud).x + (ud).y - (ub).y - (uc).x;                       \
        t0 = C11 * e0 + C12 * e1;                                           \
        t1 = C12 * e0 + C11 * e1;                                           \
        t2 = C33 * e2;                                                      \
    }

__global__ __launch_bounds__(256, 4) void pino_fused_kernel(
    const float2* __restrict__ up, const float2* __restrict__ ut,
    float* __restrict__ out) {
    const int j = blockIdx.x * 32 + threadIdx.x;
    const int i0 = (blockIdx.y * 8 + threadIdx.y) * RPT;
    const int djm = (j > 0) ? -1 : 0;
    const int djp = (j < G - 1) ? 1 : 0;
    const bool jint = (j > 0) && (j < G - 1);

    // rolling 3-row window of u_pred + 2-slot prefetch queues (distance 2)
    float2 pm0, pm1, pm2, pc0, pc1, pc2, pn0, pn1, pn2;
    float2 f0[2], f1[2], f2[2];    // up prefetch rows
    float2 tc0, tc1, tn0, tn1;
    float2 g0[2], g1[2];           // ut prefetch rows

    {
        const int rm = max(i0 - 1, 0);
        const float2* p = up + rm * G + j;
        pm0 = __ldg(p + djm); pm1 = __ldg(p); pm2 = __ldg(p + djp);
    }
    {
        const float2* p = up + i0 * G + j;
        pc0 = __ldg(p + djm); pc1 = __ldg(p); pc2 = __ldg(p + djp);
        const float2* q = p + G;  // i0+1 <= G-7, no clamp needed
        pn0 = __ldg(q + djm); pn1 = __ldg(q); pn2 = __ldg(q + djp);
    }
    {
        const int r2 = min(i0 + 2, G - 1);
        const float2* p = up + r2 * G + j;
        f0[0] = __ldg(p + djm); f1[0] = __ldg(p); f2[0] = __ldg(p + djp);
        const float2* q = ut + i0 * G + j;
        tc0 = __ldg(q); tc1 = __ldg(q + djp);
        const float2* q1 = ut + (i0 + 1) * G + j;
        tn0 = __ldg(q1); tn1 = __ldg(q1 + djp);
        const float2* q2 = ut + r2 * G + j;
        g0[0] = __ldg(q2); g1[0] = __ldg(q2 + djp);
    }

    float vr = 0.f, ve = 0.f;

    #pragma unroll
    for (int k = 0; k < RPT; k++) {
        const int i = i0 + k;

        // prefetch row i+3 into slot (k+1)&1 (consumed two iterations later)
        if (k <= RPT - 3) {
            const int rq = min(i + 3, G - 1);
            const int s = (k + 1) & 1;
            const float2* p = up + rq * G + j;
            f0[s] = __ldg(p + djm); f1[s] = __ldg(p); f2[s] = __ldg(p + djp);
            const float2* q = ut + rq * G + j;
            g0[s] = __ldg(q); g1[s] = __ldg(q + djp);
        }

        float Rx, Ry;
        if (jint && i > 0 && i < G - 1) {
            // interior 7-point stencil (u00/u22 cancel out)
            float Vx = pm1.x + pn1.x, Hx = pc0.x + pc2.x;
            float Vy = pm1.y + pn1.y, Hy = pc0.y + pc2.y;
            float Tx = 2.f * pc1.x - Vx - Hx + pn0.x + pm2.x;
            float Ty = 2.f * pc1.y - Vy - Hy + pn0.y + pm2.y;
            Rx = A2c * pc1.x - C11 * Vx - C33 * Hx + BGc * Ty;
            Ry = A2c * pc1.y - C11 * Hy - C33 * Vy + BGc * Tx;
        } else {
            // boundary: full masked 6-triangle path (verified)
            const float mA = (i < G - 1 && j < G - 1) ? 1.f : 0.f;
            const float mB = (i < G - 1 && j > 0) ? 1.f : 0.f;
            const float mC = (i > 0 && j < G - 1) ? 1.f : 0.f;
            const float mD = (i > 0 && j > 0) ? 1.f : 0.f;
            float sA0, sA1, sA2; TRI1(sA0, sA1, sA2, pc1, pc2, pn1);
            float sB0, sB1, sB2; TRI1(sB0, sB1, sB2, pc0, pc1, pn0);
            float tB0, tB1, tB2; TRI2(tB0, tB1, tB2, pc1, pn1, pn0);
            float sC0, sC1, sC2; TRI1(sC0, sC1, sC2, pm1, pm2, pc1);
            float tC0, tC1, tC2; TRI2(tC0, tC1, tC2, pm2, pc2, pc1);
            float tD0, tD1, tD2; TRI2(tD0, tD1, tD2, pm1, pc1, pc0);
            (void)sB0; (void)tB1; (void)sC1; (void)tC0;
            Rx = mA * (-0.5f) * (sA0 + sA2) + mB * 0.5f * (sB2 - tB0) +
                 mC * 0.5f * (sC0 - tC2)    + mD * 0.5f * (tD0 + tD2);
            Ry = mA * (-0.5f) * (sA1 + sA2) + mB * 0.5f * (sB1 - tB2) +
                 mC * 0.5f * (sC2 - tC1)    + mD * 0.5f * (tD1 + tD2);
        }
        vr += Rx * Rx + Ry * Ry;

        // energy of cell (i,j) on u_err; (x0.5 applied at final combine)
        if (i < G - 1 && j < G - 1) {
            float eax = pc1.x - tc0.x, eay = pc1.y - tc0.y;
            float ebx = pc2.x - tc1.x, eby = pc2.y - tc1.y;
            float ecx = pn1.x - tn0.x, ecy = pn1.y - tn0.y;
            float edx = pn2.x - tn1.x, edy = pn2.y - tn1.y;
            float d0 = ecx - eax, d1 = eby - eay, d2 = ebx + ecy - eax - eay;
            float e0 = edx - ebx, e1 = edy - ecy, e2 = edx + edy - eby - ecx;
            ve += C11 * (d0 * d0 + d1 * d1) + 2.f * C12 * (d0 * d1) +
                  C33 * (d2 * d2) +
                  C11 * (e0 * e0 + e1 * e1) + 2.f * C12 * (e0 * e1) +
                  C33 * (e2 * e2);
        }

        // shift window; consume prefetch slot k&1 (holds row i+2)
        if (k < RPT - 1) {
            const int s = k & 1;
            pm0 = pc0; pm1 = pc1; pm2 = pc2;
            pc0 = pn0; pc1 = pn1; pc2 = pn2;
            pn0 = f0[s]; pn1 = f1[s]; pn2 = f2[s];
            tc0 = tn0; tc1 = tn1;
            tn0 = g0[s]; tn1 = g1[s];
        }
    }

    // ---- block reduction ----
    #pragma unroll
    for (int o = 16; o; o >>= 1) {
        vr += __shfl_down_sync(0xFFFFFFFFu, vr, o);
        ve += __shfl_down_sync(0xFFFFFFFFu, ve, o);
    }
    __shared__ float sr[8], se[8];
    __shared__ unsigned s_last;
    if (threadIdx.x == 0) { sr[threadIdx.y] = vr; se[threadIdx.y] = ve; }
    __syncthreads();
    if (threadIdx.x == 0 && threadIdx.y == 0) {
        float a = 0.f, b = 0.f;
        #pragma unroll
        for (int q = 0; q < 8; q++) { a += sr[q]; b += se[q]; }
        int bid = blockIdx.y * gridDim.x + blockIdx.x;
        g_part[bid] = make_float2(a, b);
        __threadfence();
        unsigned old = atomicAdd(&g_cnt, 1u);
        s_last = (old == NBLOCKS - 1) ? 1u : 0u;
    }
    __syncthreads();

    // ---- last block finishes the global reduction (fixed order -> deterministic) ----
    if (s_last) {
        const int t = threadIdx.y * 32 + threadIdx.x;  // 0..255
        double a = 0.0, b = 0.0;
        #pragma unroll
        for (int q = 0; q < NBLOCKS / 256; q++) {
            float2 v = g_part[q * 256 + t];
            a += (double)v.x;
            b += (double)v.y;
        }
        #pragma unroll
        for (int o = 16; o; o >>= 1) {
            a += __shfl_down_sync(0xFFFFFFFFu, a, o);
            b += __shfl_down_sync(0xFFFFFFFFu, b, o);
        }
        __shared__ double dr[8], de[8];
        if ((t & 31) == 0) { dr[t >> 5] = a; de[t >> 5] = b; }
        __syncthreads();
        if (t == 0) {
            double ta = 0.0, tb = 0.0;
            #pragma unroll
            for (int q = 0; q < 8; q++) { ta += dr[q]; tb += de[q]; }
            double leq = ta / (2.0 * (double)G * (double)G);  // mean(R^2)
            double len = 0.5 * tb;  // total_area telescopes to 1.0
            out[0] = (float)(0.1 * leq + 0.1 * len);
            g_cnt = 0;  // reset for next graph replay
        }
    }
}

extern "C" void kernel_launch(void* const* d_in, const int* in_sizes, int n_in,
                              void* d_out, int out_size) {
    const float2* up = (const float2*)d_in[0];  // u_pred (N,2)
    const float2* ut = (const float2*)d_in[1];  // u_true (N,2)
    (void)in_sizes; (void)n_in; (void)out_size;

    dim3 blk(32, 8);
    dim3 grd(G / 32, G / (8 * RPT));  // 32 x 16 = 512 blocks, one wave
    pino_fused_kernel<<<grd, blk>>>(up, ut, (float*)d_out);
}

// round 9
// speedup vs baseline: 1.2857x; 1.1128x over previous
#include <cuda_runtime.h>

#define G 1024
#define RPT 8
#define BY 4          // block = 32 x 4 = 128 threads
#define NBLOCKS 1024  // grid 32 x 32

__device__ float2 g_part[NBLOCKS];
__device__ unsigned int g_cnt = 0;

#define C11 (1.0f / 0.91f)
#define C12 (0.3f / 0.91f)
#define C33 (0.35f / 0.91f)
#define A2c (2.0f * (C11 + C33))
#define BGc (0.5f * (C12 + C33))

// tri1 of a cell (corners a, b=a+j, c=a+i): s = C * d
#define TRI1(s0, s1, s2, ua, ub, uc)                                        \
    {                                                                       \
        float d0 = (uc).x - (ua).x;                                         \
        float d1 = (ub).y - (ua).y;                                         \
        float d2 = (ub).x + (uc).y - (ua).x - (ua).y;                       \
        s0 = C11 * d0 + C12 * d1;                                           \
        s1 = C12 * d0 + C11 * d1;                                           \
        s2 = C33 * d2;                                                      \
    }
// tri2 of a cell (corners b, d=b+i, c=d-j)
#define TRI2(t0, t1, t2, ub, ud, uc)                                        \
    {                                                                       \
        float e0 = (ud).x - (ub).x;                                         \
        float e1 = (ud).y - (uc).y;                                         \
        float e2 = (ud).x + (ud).y - (ub).y - (uc).x;                       \
        t0 = C11 * e0 + C12 * e1;                                           \
        t1 = C12 * e0 + C11 * e1;                                           \
        t2 = C33 * e2;                                                      \
    }

__global__ __launch_bounds__(128, 8) void pino_fused_kernel(
    const float2* __restrict__ up, const float2* __restrict__ ut,
    float* __restrict__ out) {
    const int j = blockIdx.x * 32 + threadIdx.x;
    const int i0 = (blockIdx.y * BY + threadIdx.y) * RPT;
    const int djm = (j > 0) ? -1 : 0;
    const int djp = (j < G - 1) ? 1 : 0;
    const bool jint = (j > 0) && (j < G - 1);

    // rolling 3-row window of u_pred + 2-slot prefetch queues (distance 2)
    float2 pm0, pm1, pm2, pc0, pc1, pc2, pn0, pn1, pn2;
    float2 f0[2], f1[2], f2[2];    // up prefetch rows
    float2 tc0, tc1, tn0, tn1;
    float2 g0[2], g1[2];           // ut prefetch rows

    {
        const int rm = max(i0 - 1, 0);
        const float2* p = up + rm * G + j;
        pm0 = __ldg(p + djm); pm1 = __ldg(p); pm2 = __ldg(p + djp);
    }
    {
        const float2* p = up + i0 * G + j;
        pc0 = __ldg(p + djm); pc1 = __ldg(p); pc2 = __ldg(p + djp);
        const float2* q = p + G;  // i0+1 <= G-7, no clamp needed
        pn0 = __ldg(q + djm); pn1 = __ldg(q); pn2 = __ldg(q + djp);
    }
    {
        const int r2 = min(i0 + 2, G - 1);
        const float2* p = up + r2 * G + j;
        f0[0] = __ldg(p + djm); f1[0] = __ldg(p); f2[0] = __ldg(p + djp);
        const float2* q = ut + i0 * G + j;
        tc0 = __ldg(q); tc1 = __ldg(q + djp);
        const float2* q1 = ut + (i0 + 1) * G + j;
        tn0 = __ldg(q1); tn1 = __ldg(q1 + djp);
        const float2* q2 = ut + r2 * G + j;
        g0[0] = __ldg(q2); g1[0] = __ldg(q2 + djp);
    }

    float vr = 0.f, ve = 0.f;

    #pragma unroll
    for (int k = 0; k < RPT; k++) {
        const int i = i0 + k;

        // prefetch row i+3 into slot (k+1)&1 (consumed two iterations later)
        if (k <= RPT - 3) {
            const int rq = min(i + 3, G - 1);
            const int s = (k + 1) & 1;
            const float2* p = up + rq * G + j;
            f0[s] = __ldg(p + djm); f1[s] = __ldg(p); f2[s] = __ldg(p + djp);
            const float2* q = ut + rq * G + j;
            g0[s] = __ldg(q); g1[s] = __ldg(q + djp);
        }

        float Rx, Ry;
        if (jint && i > 0 && i < G - 1) {
            // interior 7-point stencil (u00/u22 cancel out)
            float Vx = pm1.x + pn1.x, Hx = pc0.x + pc2.x;
            float Vy = pm1.y + pn1.y, Hy = pc0.y + pc2.y;
            float Tx = 2.f * pc1.x - Vx - Hx + pn0.x + pm2.x;
            float Ty = 2.f * pc1.y - Vy - Hy + pn0.y + pm2.y;
            Rx = A2c * pc1.x - C11 * Vx - C33 * Hx + BGc * Ty;
            Ry = A2c * pc1.y - C11 * Hy - C33 * Vy + BGc * Tx;
        } else {
            // boundary: full masked 6-triangle path (verified)
            const float mA = (i < G - 1 && j < G - 1) ? 1.f : 0.f;
            const float mB = (i < G - 1 && j > 0) ? 1.f : 0.f;
            const float mC = (i > 0 && j < G - 1) ? 1.f : 0.f;
            const float mD = (i > 0 && j > 0) ? 1.f : 0.f;
            float sA0, sA1, sA2; TRI1(sA0, sA1, sA2, pc1, pc2, pn1);
            float sB0, sB1, sB2; TRI1(sB0, sB1, sB2, pc0, pc1, pn0);
            float tB0, tB1, tB2; TRI2(tB0, tB1, tB2, pc1, pn1, pn0);
            float sC0, sC1, sC2; TRI1(sC0, sC1, sC2, pm1, pm2, pc1);
            float tC0, tC1, tC2; TRI2(tC0, tC1, tC2, pm2, pc2, pc1);
            float tD0, tD1, tD2; TRI2(tD0, tD1, tD2, pm1, pc1, pc0);
            (void)sB0; (void)tB1; (void)sC1; (void)tC0;
            Rx = mA * (-0.5f) * (sA0 + sA2) + mB * 0.5f * (sB2 - tB0) +
                 mC * 0.5f * (sC0 - tC2)    + mD * 0.5f * (tD0 + tD2);
            Ry = mA * (-0.5f) * (sA1 + sA2) + mB * 0.5f * (sB1 - tB2) +
                 mC * 0.5f * (sC2 - tC1)    + mD * 0.5f * (tD1 + tD2);
        }
        vr += Rx * Rx + Ry * Ry;

        // energy of cell (i,j) on u_err; (x0.5 applied at final combine)
        if (i < G - 1 && j < G - 1) {
            float eax = pc1.x - tc0.x, eay = pc1.y - tc0.y;
            float ebx = pc2.x - tc1.x, eby = pc2.y - tc1.y;
            float ecx = pn1.x - tn0.x, ecy = pn1.y - tn0.y;
            float edx = pn2.x - tn1.x, edy = pn2.y - tn1.y;
            float d0 = ecx - eax, d1 = eby - eay, d2 = ebx + ecy - eax - eay;
            float e0 = edx - ebx, e1 = edy - ecy, e2 = edx + edy - eby - ecx;
            ve += C11 * (d0 * d0 + d1 * d1) + 2.f * C12 * (d0 * d1) +
                  C33 * (d2 * d2) +
                  C11 * (e0 * e0 + e1 * e1) + 2.f * C12 * (e0 * e1) +
                  C33 * (e2 * e2);
        }

        // shift window; consume prefetch slot k&1 (holds row i+2)
        if (k < RPT - 1) {
            const int s = k & 1;
            pm0 = pc0; pm1 = pc1; pm2 = pc2;
            pc0 = pn0; pc1 = pn1; pc2 = pn2;
            pn0 = f0[s]; pn1 = f1[s]; pn2 = f2[s];
            tc0 = tn0; tc1 = tn1;
            tn0 = g0[s]; tn1 = g1[s];
        }
    }

    // ---- block reduction (4 warps) ----
    #pragma unroll
    for (int o = 16; o; o >>= 1) {
        vr += __shfl_down_sync(0xFFFFFFFFu, vr, o);
        ve += __shfl_down_sync(0xFFFFFFFFu, ve, o);
    }
    __shared__ float sr[BY], se[BY];
    __shared__ unsigned s_last;
    if (threadIdx.x == 0) { sr[threadIdx.y] = vr; se[threadIdx.y] = ve; }
    __syncthreads();
    if (threadIdx.x == 0 && threadIdx.y == 0) {
        float a = 0.f, b = 0.f;
        #pragma unroll
        for (int q = 0; q < BY; q++) { a += sr[q]; b += se[q]; }
        int bid = blockIdx.y * gridDim.x + blockIdx.x;
        g_part[bid] = make_float2(a, b);
        __threadfence();
        unsigned old = atomicAdd(&g_cnt, 1u);
        s_last = (old == NBLOCKS - 1) ? 1u : 0u;
    }
    __syncthreads();

    // ---- last block finishes the global reduction (fixed order -> deterministic) ----
    if (s_last) {
        const int t = threadIdx.y * 32 + threadIdx.x;  // 0..127
        double a = 0.0, b = 0.0;
        #pragma unroll
        for (int q = 0; q < NBLOCKS / 128; q++) {
            float2 v = g_part[q * 128 + t];
            a += (double)v.x;
            b += (double)v.y;
        }
        #pragma unroll
        for (int o = 16; o; o >>= 1) {
            a += __shfl_down_sync(0xFFFFFFFFu, a, o);
            b += __shfl_down_sync(0xFFFFFFFFu, b, o);
        }
        __shared__ double dr[BY], de[BY];
        if ((t & 31) == 0) { dr[t >> 5] = a; de[t >> 5] = b; }
        __syncthreads();
        if (t == 0) {
            double ta = 0.0, tb = 0.0;
            #pragma unroll
            for (int q = 0; q < BY; q++) { ta += dr[q]; tb += de[q]; }
            double leq = ta / (2.0 * (double)G * (double)G);  // mean(R^2)
            double len = 0.5 * tb;  // total_area telescopes to 1.0
            out[0] = (float)(0.1 * leq + 0.1 * len);
            g_cnt = 0;  // reset for next graph replay
        }
    }
}

extern "C" void kernel_launch(void* const* d_in, const int* in_sizes, int n_in,
                              void* d_out, int out_size) {
    const float2* up = (const float2*)d_in[0];  // u_pred (N,2)
    const float2* ut = (const float2*)d_in[1];  // u_true (N,2)
    (void)in_sizes; (void)n_in; (void)out_size;

    dim3 blk(32, BY);
    dim3 grd(G / 32, G / (BY * RPT));  // 32 x 32 = 1024 blocks of 128 threads
    pino_fused_kernel<<<grd, blk>>>(up, ut, (float*)d_out);
}